// round 2
// baseline (speedup 1.0000x reference)
#include <cuda_runtime.h>

// Problem dims (fixed)
#define S_LEN 128
#define B_SZ  64
#define E_DIM 512
#define PL    160
#define PD    512
#define H_DIM 1024

#define NBLK 148
#define NTHR 256

// ---------------- persistent scratch (device globals; no runtime alloc) ----------------
__device__ float g_hA[B_SZ * H_DIM];
__device__ float g_hB[B_SZ * H_DIM];
__device__ float g_Q[B_SZ * PD];
__device__ float g_ctx[B_SZ * PD];
__device__ unsigned int g_count;
__device__ unsigned int g_release;

// ---------------- grid-wide epoch barrier ----------------
// Requires all NBLK blocks co-resident (NBLK <= SM count). Producer-side
// __threadfence orders stores before the arrive; consumer-side __threadfence
// emits CCTL.IVALL on sm_103a (gpu scope >= cluster), invalidating stale L1.
__device__ __forceinline__ void gsync(unsigned int epoch) {
    __syncthreads();
    if (threadIdx.x == 0) {
        __threadfence();
        unsigned int arrived = atomicAdd(&g_count, 1u) + 1u;
        if (arrived == (unsigned)NBLK * epoch) {
            atomicExch(&g_release, epoch);
        } else {
            while (*(volatile unsigned int*)&g_release < epoch) {
                __nanosleep(40);
            }
        }
        __threadfence();
    }
    __syncthreads();
}

// ---------------- fp32 dot helper (float4, 4 accumulators) ----------------
__device__ __forceinline__ float dot4N(const float* __restrict__ w,
                                       const float* __restrict__ x, int n4) {
    const float4* w4 = (const float4*)w;
    const float4* x4 = (const float4*)x;
    float a0 = 0.f, a1 = 0.f, a2 = 0.f, a3 = 0.f;
#pragma unroll 4
    for (int i = 0; i < n4; i++) {
        float4 wv = w4[i];
        float4 xv = x4[i];
        a0 = fmaf(wv.x, xv.x, a0);
        a1 = fmaf(wv.y, xv.y, a1);
        a2 = fmaf(wv.z, xv.z, a2);
        a3 = fmaf(wv.w, xv.w, a3);
    }
    return (a0 + a1) + (a2 + a3);
}

// ---------------- gates job: one (j, b-half) pair; lanes = 32 batches ----------------
__device__ __forceinline__ void gates_job(
    int job, int lane, int t,
    const float* __restrict__ hcur, float* __restrict__ hnext,
    const float* __restrict__ incoming,
    const float* __restrict__ wih, const float* __restrict__ whh,
    const float* __restrict__ bih, const float* __restrict__ bhh,
    const int* __restrict__ length,
    float* __restrict__ out, int write_last)
{
    int j = job >> 1;
    int b = ((job & 1) << 5) | lane;

    const float* xt = incoming + ((size_t)t * B_SZ + b) * E_DIM;
    const float* cb = g_ctx + (size_t)b * PD;
    const float* hb = hcur + (size_t)b * H_DIM;

    float gi[3], gh[3];
#pragma unroll
    for (int g = 0; g < 3; g++) {
        const float* wr = wih + (size_t)(g * H_DIM + j) * (E_DIM + PD);
        float acc = bih[g * H_DIM + j];
        acc += dot4N(wr, xt, E_DIM / 4);
        acc += dot4N(wr + E_DIM, cb, PD / 4);
        gi[g] = acc;
        const float* hr = whh + (size_t)(g * H_DIM + j) * H_DIM;
        gh[g] = bhh[g * H_DIM + j] + dot4N(hr, hb, H_DIM / 4);
    }

    float r = 1.f / (1.f + __expf(-(gi[0] + gh[0])));
    float z = 1.f / (1.f + __expf(-(gi[1] + gh[1])));
    float n = tanhf(gi[2] + r * gh[2]);
    float hn = (1.f - z) * n + z * hb[j];
    if (length[b] <= t) hn = 0.f;

    hnext[(size_t)b * H_DIM + j] = hn;
    out[((size_t)t * B_SZ + b) * H_DIM + j] = hn;
    if (write_last && t == S_LEN - 1) {
        out[(size_t)S_LEN * B_SZ * H_DIM + (size_t)b * H_DIM + j] = hn;
    }
}

// ---------------- init: h0 broadcast + barrier reset ----------------
__global__ void init_kernel(const float* __restrict__ h_init) {
    int b = blockIdx.x;
    for (int k = threadIdx.x; k < H_DIM; k += blockDim.x)
        g_hA[(size_t)b * H_DIM + k] = h_init[k];
    if (b == 0 && threadIdx.x == 0) {
        g_count = 0u;
        g_release = 0u;
    }
}

// ---------------- persistent recurrent kernel ----------------
__global__ void __launch_bounds__(NTHR, 1) gru_kernel(
    const float* __restrict__ incoming,
    const float* __restrict__ post,
    const float* __restrict__ wih,
    const float* __restrict__ whh,
    const float* __restrict__ bih,
    const float* __restrict__ bhh,
    const float* __restrict__ wq,
    const float* __restrict__ bq,
    const int* __restrict__ length,
    const int* __restrict__ post_length,
    float* __restrict__ out,
    int write_last)
{
    __shared__ float s_wq[4][1028];   // 4 wq rows, padded (bank-conflict-free LDS.128)
    __shared__ float s_q[PD];
    __shared__ float s_sc[PL];
    __shared__ float s_stat[2];       // [0]=max, [1]=1/sum

    const int tid = threadIdx.x;
    const int bx = blockIdx.x;
    unsigned int ep = 0;

    for (int t = 0; t < S_LEN; t++) {
        const float* hcur = (t & 1) ? g_hB : g_hA;
        float* hnext      = (t & 1) ? g_hA : g_hB;

        // ---------- Phase 1: Q = h @ wq^T + bq   (blocks 0..127, 4 d-rows each) ----------
        if (bx < 128) {
            int dbase = bx * 4;
            for (int idx = tid; idx < 4 * H_DIM; idx += NTHR) {
                int r = idx >> 10, k = idx & 1023;
                s_wq[r][k] = wq[(size_t)(dbase + r) * H_DIM + k];
            }
            __syncthreads();
            int b = tid >> 2, ds = tid & 3;
            const float4* h4 = (const float4*)(hcur + (size_t)b * H_DIM);
            const float4* w4 = (const float4*)&s_wq[ds][0];
            float a0 = 0.f, a1 = 0.f, a2 = 0.f, a3 = 0.f;
#pragma unroll 4
            for (int i = 0; i < H_DIM / 4; i++) {
                float4 wv = w4[i];
                float4 hv = h4[i];
                a0 = fmaf(wv.x, hv.x, a0);
                a1 = fmaf(wv.y, hv.y, a1);
                a2 = fmaf(wv.z, hv.z, a2);
                a3 = fmaf(wv.w, hv.w, a3);
            }
            g_Q[(size_t)b * PD + dbase + ds] = (a0 + a1) + (a2 + a3) + bq[dbase + ds];
        }
        ep++; gsync(ep);

        // ---------- Phase 2: attention (blocks 0..63, one batch each) ----------
        if (bx < B_SZ) {
            int b = bx;
            s_q[tid] = g_Q[(size_t)b * PD + tid];
            s_q[tid + 256] = g_Q[(size_t)b * PD + 256 + tid];
            __syncthreads();

            int pl = post_length[b];
            if (tid < PL) {
                const float4* pr = (const float4*)(post + ((size_t)tid * B_SZ + b) * PD);
                const float4* q4 = (const float4*)s_q;
                float a0 = 0.f, a1 = 0.f, a2 = 0.f, a3 = 0.f;
#pragma unroll 4
                for (int i = 0; i < PD / 4; i++) {
                    float4 pv = pr[i];
                    float4 qv = q4[i];
                    a0 = fmaf(pv.x, qv.x, a0);
                    a1 = fmaf(pv.y, qv.y, a1);
                    a2 = fmaf(pv.z, qv.z, a2);
                    a3 = fmaf(pv.w, qv.w, a3);
                }
                float sc = (a0 + a1) + (a2 + a3);
                s_sc[tid] = (tid < pl) ? sc : -1e30f;
            }
            __syncthreads();

            if (tid < 32) {  // max reduce over 160
                float m = -1e30f;
                for (int p = tid; p < PL; p += 32) m = fmaxf(m, s_sc[p]);
#pragma unroll
                for (int o = 16; o > 0; o >>= 1)
                    m = fmaxf(m, __shfl_xor_sync(0xffffffffu, m, o));
                if (tid == 0) s_stat[0] = m;
            }
            __syncthreads();
            if (tid < PL) s_sc[tid] = __expf(s_sc[tid] - s_stat[0]);
            __syncthreads();
            if (tid < 32) {  // sum reduce
                float s = 0.f;
                for (int p = tid; p < PL; p += 32) s += s_sc[p];
#pragma unroll
                for (int o = 16; o > 0; o >>= 1)
                    s += __shfl_xor_sync(0xffffffffu, s, o);
                if (tid == 0) s_stat[1] = 1.f / s;
            }
            __syncthreads();

            // context: each thread 2 consecutive d's (coalesced float2 column pass)
            {
                int d = tid * 2;
                const float* pb = post + (size_t)b * PD + d;
                float c0 = 0.f, c1 = 0.f;
#pragma unroll 4
                for (int p = 0; p < PL; p++) {
                    float a = s_sc[p];
                    float2 v = *(const float2*)(pb + (size_t)p * B_SZ * PD);
                    c0 = fmaf(a, v.x, c0);
                    c1 = fmaf(a, v.y, c1);
                }
                float inv = s_stat[1];
                g_ctx[(size_t)b * PD + d] = c0 * inv;
                g_ctx[(size_t)b * PD + d + 1] = c1 * inv;
            }
        }
        ep++; gsync(ep);

        // ---------- Phase 3: GRU gates (balanced 2-round warp-job schedule) ----------
        {
            int wid = tid >> 5, lane = tid & 31;
            int gw = bx * 8 + wid;                 // round 1: jobs 0..1183
            gates_job(gw, lane, t, hcur, hnext, incoming, wih, whh, bih, bhh,
                      length, out, write_last);
            int j2 = 1184 + wid * NBLK + bx;       // round 2: jobs 1184..2047, spread over all SMs
            if (j2 < 2048)
                gates_job(j2, lane, t, hcur, hnext, incoming, wih, whh, bih, bhh,
                          length, out, write_last);
        }
        ep++; gsync(ep);
    }
}

// ---------------- launch ----------------
extern "C" void kernel_launch(void* const* d_in, const int* in_sizes, int n_in,
                              void* d_out, int out_size) {
    const float* incoming    = (const float*)d_in[0];
    const float* post        = (const float*)d_in[1];
    const float* h_init      = (const float*)d_in[2];
    const float* wih         = (const float*)d_in[3];
    const float* whh         = (const float*)d_in[4];
    const float* bih         = (const float*)d_in[5];
    const float* bhh         = (const float*)d_in[6];
    const float* wq          = (const float*)d_in[7];
    const float* bq          = (const float*)d_in[8];
    const int*   length      = (const int*)d_in[9];
    const int*   post_length = (const int*)d_in[10];
    float* out = (float*)d_out;

    int write_last = (out_size >= S_LEN * B_SZ * H_DIM + B_SZ * H_DIM) ? 1 : 0;

    init_kernel<<<B_SZ, 256>>>(h_init);
    gru_kernel<<<NBLK, NTHR>>>(incoming, post, wih, whh, bih, bhh, wq, bq,
                               length, post_length, out, write_last);
}

// round 3
// speedup vs baseline: 4.0679x; 4.0679x over previous
#include <cuda_runtime.h>

#define S_LEN 128
#define B_SZ  64
#define E_DIM 512
#define PL    160
#define PD    512
#define H_DIM 1024

#define NBLK 128
#define NTHR 256

typedef unsigned long long u64;

// ---------------- persistent scratch (device globals) ----------------
__device__ float2 g_H2T[2][(H_DIM / 2) * B_SZ];              // [buf][k2*64+b]
__device__ float2 g_CTX2T[(PD / 2) * B_SZ];                  // [d2*64+b]
__device__ float2 g_INC2T[(size_t)S_LEN * (E_DIM / 2) * B_SZ];  // [t][k2][b], 16MB
__device__ float  g_Qrow[B_SZ * PD];                         // [b][d]
__device__ unsigned int g_count;
__device__ unsigned int g_release;

// ---------------- packed f32x2 helpers ----------------
__device__ __forceinline__ void ffma2(u64& d, u64 a, u64 b) {
    asm("fma.rn.f32x2 %0, %1, %2, %0;" : "+l"(d) : "l"(a), "l"(b));
}
__device__ __forceinline__ float sum2(u64 v) {
    float2 f;
    f.x = __int_as_float((unsigned)(v & 0xffffffffULL));
    f.y = __int_as_float((unsigned)(v >> 32));
    return f.x + f.y;
}

// ---------------- grid-wide epoch barrier ----------------
__device__ __forceinline__ void gsync(unsigned int epoch) {
    __syncthreads();
    if (threadIdx.x == 0) {
        __threadfence();
        unsigned int arrived = atomicAdd(&g_count, 1u) + 1u;
        if (arrived == (unsigned)NBLK * epoch) {
            atomicExch(&g_release, epoch);
        } else {
            while (*(volatile unsigned int*)&g_release < epoch) {
                __nanosleep(40);
            }
        }
        __threadfence();
    }
    __syncthreads();
}

// ---------------- pre-pass: transpose incoming, broadcast h0, reset barrier ----------------
__global__ void pre_kernel(const float* __restrict__ incoming,
                           const float* __restrict__ h_init) {
    int t = blockIdx.x;   // 0..127
    int tid = threadIdx.x;
    // incoming[t][b][k] -> g_INC2T[t][k2][b]
    for (int idx = tid; idx < (E_DIM / 2) * B_SZ; idx += NTHR) {
        int k2 = idx >> 6, b = idx & 63;
        const float* src = incoming + ((size_t)t * B_SZ + b) * E_DIM + 2 * k2;
        g_INC2T[(size_t)t * ((E_DIM / 2) * B_SZ) + idx] = make_float2(src[0], src[1]);
    }
    // h_init broadcast: block t fills its slice of g_H2T[0]
    {
        int g = t * 256 + tid;           // 128 blocks * 256 = 32768 = (H/2)*B
        int k2 = g >> 6;
        g_H2T[0][g] = make_float2(h_init[2 * k2], h_init[2 * k2 + 1]);
    }
    if (t == 0 && tid == 0) { g_count = 0u; g_release = 0u; }
}

// ---------------- persistent recurrent kernel ----------------
__global__ void __launch_bounds__(NTHR, 1) gru_kernel(
    const float* __restrict__ post,
    const float* __restrict__ wih,
    const float* __restrict__ whh,
    const float* __restrict__ bih,
    const float* __restrict__ bhh,
    const float* __restrict__ wq,
    const float* __restrict__ bq,
    const int* __restrict__ length,
    const int* __restrict__ post_length,
    float* __restrict__ out,
    int write_last)
{
    __shared__ float2 s_x[64][32];               // K-chunk: 64 k2 x 32 b   (16KB)
    __shared__ __align__(16) float s_q[PD];      // attention query
    __shared__ float s_sc[PL];
    __shared__ u64   s_e2[PL];                   // packed {e,e}
    __shared__ float s_stat[2];                  // [0]=max, [1]=1/sum

    const int tid = threadIdx.x;
    const int bx = blockIdx.x;
    const int wid = tid >> 5;
    const int lane = tid & 31;

    // gates-phase constants for this block
    const int g_half  = bx & 1;
    const int g_jbase = (bx >> 1) * 16;
    const int g_j0    = g_jbase + wid * 2;
    const int g_b     = g_half * 32 + lane;
    const int g_len   = length[g_b];

    unsigned int ep = 0;

    for (int t = 0; t < S_LEN; t++) {
        const float2* hcur = g_H2T[t & 1];
        float2* hnext      = g_H2T[(t & 1) ^ 1];

        // ================= Phase 1: Q = h @ wq^T + bq =================
        // 1024 warp-jobs: (d in [0,512), half in {0,1})
        {
            int gw = bx * 8 + wid;
            int d = gw >> 1;
            int half = gw & 1;
            int b = half * 32 + lane;
            const ulonglong2* w2 = (const ulonglong2*)(wq + (size_t)d * H_DIM);
            const u64* hsrc = (const u64*)hcur;
            u64 a0 = 0ull, a1 = 0ull;
#pragma unroll 4
            for (int k4 = 0; k4 < H_DIM / 4; k4++) {
                ulonglong2 w = w2[k4];
                u64 xa = hsrc[(2 * k4) * B_SZ + b];
                u64 xb = hsrc[(2 * k4 + 1) * B_SZ + b];
                ffma2(a0, w.x, xa);
                ffma2(a1, w.y, xb);
            }
            g_Qrow[(size_t)b * PD + d] = sum2(a0) + sum2(a1) + bq[d];
        }
        ep++; gsync(ep);

        // ================= Phase 2: attention (blocks 0..63 = batch) =================
        if (bx < B_SZ) {
            const int b = bx;
            s_q[tid] = g_Qrow[(size_t)b * PD + tid];
            s_q[tid + 256] = g_Qrow[(size_t)b * PD + 256 + tid];
            __syncthreads();

            int pl = post_length[b];
            const ulonglong2* qq = (const ulonglong2*)s_q;
            // scores: warp per p, lanes along d (coalesced)
            for (int p = wid; p < PL; p += 8) {
                const ulonglong2* pp =
                    (const ulonglong2*)(post + ((size_t)p * B_SZ + b) * PD);
                u64 a0 = 0ull, a1 = 0ull;
#pragma unroll 4
                for (int i = lane; i < PD / 4; i += 32) {
                    ulonglong2 pv = pp[i];
                    ulonglong2 qv = qq[i];
                    ffma2(a0, pv.x, qv.x);
                    ffma2(a1, pv.y, qv.y);
                }
                float s = sum2(a0) + sum2(a1);
#pragma unroll
                for (int o = 16; o > 0; o >>= 1)
                    s += __shfl_xor_sync(0xffffffffu, s, o);
                if (lane == 0) s_sc[p] = (p < pl) ? s : -1e30f;
            }
            __syncthreads();

            if (tid < 32) {
                float m = -1e30f;
                for (int p = tid; p < PL; p += 32) m = fmaxf(m, s_sc[p]);
#pragma unroll
                for (int o = 16; o > 0; o >>= 1)
                    m = fmaxf(m, __shfl_xor_sync(0xffffffffu, m, o));
                if (tid == 0) s_stat[0] = m;
            }
            __syncthreads();
            if (tid < PL) {
                float e = __expf(s_sc[tid] - s_stat[0]);
                s_sc[tid] = e;
                float2 ee = make_float2(e, e);
                s_e2[tid] = *(u64*)&ee;
            }
            __syncthreads();
            if (tid < 32) {
                float s = 0.f;
                for (int p = tid; p < PL; p += 32) s += s_sc[p];
#pragma unroll
                for (int o = 16; o > 0; o >>= 1)
                    s += __shfl_xor_sync(0xffffffffu, s, o);
                if (tid == 0) s_stat[1] = 1.f / s;
            }
            __syncthreads();

            // context: thread = d-pair (d = 2*tid); packed FFMA2; write transposed
            {
                const u64* pb = (const u64*)post + (size_t)b * (PD / 2) + tid;
                u64 c2 = 0ull;
#pragma unroll 4
                for (int p = 0; p < PL; p++)
                    ffma2(c2, s_e2[p], pb[(size_t)p * (B_SZ * PD / 2)]);
                float inv = s_stat[1];
                float lo = __int_as_float((unsigned)(c2 & 0xffffffffULL));
                float hi = __int_as_float((unsigned)(c2 >> 32));
                g_CTX2T[tid * B_SZ + b] = make_float2(lo * inv, hi * inv);
            }
        }
        ep++; gsync(ep);

        // ================= Phase 3: GRU gates =================
        // block = (b-half, 16 j's); warp = 2 j's; lanes = 32 batches of half
        {
            u64 acc[2][2][3];
#pragma unroll
            for (int p = 0; p < 2; p++)
#pragma unroll
                for (int jj = 0; jj < 2; jj++)
#pragma unroll
                    for (int g = 0; g < 3; g++) acc[p][jj][g] = 0ull;

#pragma unroll
            for (int part = 0; part < 2; part++) {
                const float* W = part ? whh : wih;
                const ulonglong2* wr[2][3];
#pragma unroll
                for (int jj = 0; jj < 2; jj++)
#pragma unroll
                    for (int g = 0; g < 3; g++)
                        wr[jj][g] = (const ulonglong2*)(W +
                            ((size_t)(g * H_DIM) + g_j0 + jj) * (size_t)1024);

                for (int chunk = 0; chunk < 8; chunk++) {
                    const float2* src;
                    if (part) src = hcur + chunk * 64 * B_SZ;
                    else if (chunk < 4)
                        src = g_INC2T + ((size_t)t * (E_DIM / 2) + chunk * 64) * B_SZ;
                    else
                        src = g_CTX2T + (size_t)(chunk - 4) * 64 * B_SZ;

                    // cooperative chunk load: 64 k2 x 32 b
#pragma unroll
                    for (int i = 0; i < 8; i++) {
                        int row = (tid >> 5) + i * 8;
                        s_x[row][lane] = src[row * B_SZ + g_half * 32 + lane];
                    }
                    __syncthreads();

                    const int kw = chunk * 32;
#pragma unroll 4
                    for (int k4 = 0; k4 < 32; k4++) {
                        u64 xa = *(const u64*)&s_x[2 * k4][lane];
                        u64 xb = *(const u64*)&s_x[2 * k4 + 1][lane];
#pragma unroll
                        for (int jj = 0; jj < 2; jj++)
#pragma unroll
                            for (int g = 0; g < 3; g++) {
                                ulonglong2 w = wr[jj][g][kw + k4];
                                ffma2(acc[part][jj][g], w.x, xa);
                                ffma2(acc[part][jj][g], w.y, xb);
                            }
                    }
                    __syncthreads();
                }
            }

            // combine + activations + writes
            float2 hprev2 = hcur[(g_j0 >> 1) * B_SZ + g_b];
            float hp[2] = { hprev2.x, hprev2.y };
            float hn[2];
#pragma unroll
            for (int jj = 0; jj < 2; jj++) {
                int j = g_j0 + jj;
                float ir  = sum2(acc[0][jj][0]) + bih[j];
                float iz  = sum2(acc[0][jj][1]) + bih[H_DIM + j];
                float inn = sum2(acc[0][jj][2]) + bih[2 * H_DIM + j];
                float hr  = sum2(acc[1][jj][0]) + bhh[j];
                float hz  = sum2(acc[1][jj][1]) + bhh[H_DIM + j];
                float hnn = sum2(acc[1][jj][2]) + bhh[2 * H_DIM + j];
                float r = 1.f / (1.f + __expf(-(ir + hr)));
                float z = 1.f / (1.f + __expf(-(iz + hz)));
                float n = tanhf(inn + r * hnn);
                hn[jj] = (1.f - z) * n + z * hp[jj];
                if (g_len <= t) hn[jj] = 0.f;
            }
            float2 hv = make_float2(hn[0], hn[1]);
            hnext[(g_j0 >> 1) * B_SZ + g_b] = hv;
            *(float2*)&out[((size_t)t * B_SZ + g_b) * H_DIM + g_j0] = hv;
            if (write_last && t == S_LEN - 1) {
                *(float2*)&out[(size_t)S_LEN * B_SZ * H_DIM +
                               (size_t)g_b * H_DIM + g_j0] = hv;
            }
        }
        ep++; gsync(ep);
    }
}

// ---------------- launch ----------------
extern "C" void kernel_launch(void* const* d_in, const int* in_sizes, int n_in,
                              void* d_out, int out_size) {
    const float* incoming    = (const float*)d_in[0];
    const float* post        = (const float*)d_in[1];
    const float* h_init      = (const float*)d_in[2];
    const float* wih         = (const float*)d_in[3];
    const float* whh         = (const float*)d_in[4];
    const float* bih         = (const float*)d_in[5];
    const float* bhh         = (const float*)d_in[6];
    const float* wq          = (const float*)d_in[7];
    const float* bq          = (const float*)d_in[8];
    const int*   length      = (const int*)d_in[9];
    const int*   post_length = (const int*)d_in[10];
    float* out = (float*)d_out;

    int write_last = (out_size >= S_LEN * B_SZ * H_DIM + B_SZ * H_DIM) ? 1 : 0;

    pre_kernel<<<S_LEN, NTHR>>>(incoming, h_init);
    gru_kernel<<<NBLK, NTHR>>>(post, wih, whh, bih, bhh, wq, bq,
                               length, post_length, out, write_last);
}